// round 2
// baseline (speedup 1.0000x reference)
#include <cuda_runtime.h>

#define BATCH    1024
#define NS       64
#define F2_T     (BATCH * NS / 2)   // float2 stride per timestep = 32768
#define SHIFT_C  4.5f
#define RESCALE_CHUNKS 4            // rescale every 4 chunks * 4 steps = 16 steps

// ---- packed f32x2 helpers (sm_103a) ----
__device__ __forceinline__ unsigned long long ffma2(unsigned long long a,
                                                    unsigned long long b,
                                                    unsigned long long c) {
    unsigned long long d;
    asm("fma.rn.f32x2 %0, %1, %2, %3;" : "=l"(d) : "l"(a), "l"(b), "l"(c));
    return d;
}
__device__ __forceinline__ unsigned long long fadd2(unsigned long long a,
                                                    unsigned long long b) {
    unsigned long long d;
    asm("add.rn.f32x2 %0, %1, %2;" : "=l"(d) : "l"(a), "l"(b));
    return d;
}
__device__ __forceinline__ unsigned long long pack2(float lo, float hi) {
    unsigned long long d;
    asm("mov.b64 %0, {%1, %2};" : "=l"(d)
        : "r"(__float_as_uint(lo)), "r"(__float_as_uint(hi)));
    return d;
}
__device__ __forceinline__ float lo32(unsigned long long v) {
    return __uint_as_float((unsigned)(v & 0xffffffffull));
}
__device__ __forceinline__ float hi32(unsigned long long v) {
    return __uint_as_float((unsigned)(v >> 32));
}

__global__ void __launch_bounds__(32, 8)
crf_forward_kernel(const float* __restrict__ em,
                   const int*   __restrict__ seq,
                   const float* __restrict__ start,
                   const float* __restrict__ stop,
                   const float* __restrict__ trans,
                   float*       __restrict__ out)
{
    // double-buffered alpha (linear domain, drifting scale)
    __shared__ __align__(16) float2 abuf[2][NS / 2];

    const int lane = threadIdx.x;        // blockDim.x == 32
    const int b    = blockIdx.x;         // one batch per warp

    // ---- one-time: E = exp(trans - c) for my two output states, in regs ----
    unsigned long long E0[32], E1[32];
    {
        const float4* tr0 = (const float4*)(trans + (2 * lane)     * NS);
        const float4* tr1 = (const float4*)(trans + (2 * lane + 1) * NS);
#pragma unroll
        for (int j = 0; j < 16; j++) {
            float4 r0 = __ldg(tr0 + j);
            float4 r1 = __ldg(tr1 + j);
            E0[2 * j]     = pack2(__expf(r0.x - SHIFT_C), __expf(r0.y - SHIFT_C));
            E0[2 * j + 1] = pack2(__expf(r0.z - SHIFT_C), __expf(r0.w - SHIFT_C));
            E1[2 * j]     = pack2(__expf(r1.x - SHIFT_C), __expf(r1.y - SHIFT_C));
            E1[2 * j + 1] = pack2(__expf(r1.z - SHIFT_C), __expf(r1.w - SHIFT_C));
        }
    }

    const int L = seq[b];
    const float2* embase = (const float2*)em + (unsigned)b * (NS / 2) + lane;

    // ---- init: a = exp(start + em_0) ----
    float2 st2  = ((const float2*)start)[lane];
    float2 em0  = __ldg(embase);
    float2 cur;
    cur.x = __expf(st2.x + em0.x);
    cur.y = __expf(st2.y + em0.y);
    abuf[0][lane] = cur;
    float C = 0.0f;
    float2 sp2 = ((const float2*)stop)[lane];
    const float estop0 = __expf(sp2.x);
    const float estop1 = __expf(sp2.y);
    __syncwarp();

    // ---- 4-deep emission prefetch ring (exp applied at load, off-chain) ----
    float2 ring[4];
#pragma unroll
    for (int i = 0; i < 4; i++) {
        int tt = 1 + i;
        if (tt < L) {
            float2 e = __ldg(embase + (unsigned)tt * F2_T);
            ring[i].x = __expf(e.x);
            ring[i].y = __expf(e.y);
        } else {
            ring[i].x = 1.0f; ring[i].y = 1.0f;
        }
    }

    // One step: read abuf[RD], write abuf[WR], single syncwarp.
#define CRF_BODY(eexp_, RD, WR)                                                \
    do {                                                                       \
        unsigned long long acc00 = 0ull, acc01 = 0ull;                         \
        unsigned long long acc10 = 0ull, acc11 = 0ull;                         \
        const ulonglong2* a2 = (const ulonglong2*)abuf[RD];                    \
        _Pragma("unroll")                                                      \
        for (int j = 0; j < 16; j++) {                                         \
            ulonglong2 av = a2[j];                                             \
            acc00 = ffma2(av.x, E0[2 * j],     acc00);                         \
            acc01 = ffma2(av.y, E0[2 * j + 1], acc01);                         \
            acc10 = ffma2(av.x, E1[2 * j],     acc10);                         \
            acc11 = ffma2(av.y, E1[2 * j + 1], acc11);                         \
        }                                                                      \
        unsigned long long va = fadd2(acc00, acc01);                           \
        unsigned long long vb = fadd2(acc10, acc11);                           \
        cur.x = (lo32(va) + hi32(va)) * (eexp_).x;                             \
        cur.y = (lo32(vb) + hi32(vb)) * (eexp_).y;                             \
        abuf[WR][lane] = cur;                                                  \
        __syncwarp();                                                          \
    } while (0)

#define CRF_STEP(tcur_, slot_, RD, WR)                                         \
    do {                                                                       \
        float2 ee = ring[slot_];                                               \
        int tp = (tcur_) + 4;                                                  \
        if (tp < L) {                                                          \
            float2 e = __ldg(embase + (unsigned)tp * F2_T);                    \
            ring[slot_].x = __expf(e.x);                                       \
            ring[slot_].y = __expf(e.y);                                       \
        }                                                                      \
        CRF_BODY(ee, RD, WR);                                                  \
    } while (0)

    int t = 1;
    int resc = RESCALE_CHUNKS;
    for (; t + 3 < L; t += 4) {
        CRF_STEP(t,     0, 0, 1);
        CRF_STEP(t + 1, 1, 1, 0);
        CRF_STEP(t + 2, 2, 0, 1);
        CRF_STEP(t + 3, 3, 1, 0);
        if (--resc == 0) {                 // every 16 steps: exact rescale
            resc = RESCALE_CHUNKS;
            float m = __shfl_sync(0xffffffffu, cur.x, 0);
            m = fmaxf(m, 1e-30f);
            float rv = __fdividef(1.0f, m);
            cur.x *= rv; cur.y *= rv;
            abuf[0][lane] = cur;           // parity is back at buf0
            __syncwarp();
            C += __logf(m);
        }
    }
    // tail: up to 3 steps, parities continue 0->1, 1->0, 0->1
    if (t < L) { CRF_BODY(ring[0], 0, 1); t++; }
    if (t < L) { CRF_BODY(ring[1], 1, 0); t++; }
    if (t < L) { CRF_BODY(ring[2], 0, 1); }

    // ---- finalize: logZ = log(sum_s a[s]*exp(stop[s])) + C + c*(L-1) ----
    float z = cur.x * estop0 + cur.y * estop1;
#pragma unroll
    for (int o = 16; o; o >>= 1)
        z += __shfl_xor_sync(0xffffffffu, z, o);
    if (lane == 0)
        out[b] = __logf(z) + C + SHIFT_C * (float)(L - 1);
}

extern "C" void kernel_launch(void* const* d_in, const int* in_sizes, int n_in,
                              void* d_out, int out_size)
{
    const float* em    = (const float*)d_in[0];
    const int*   seq   = (const int*)d_in[1];
    const float* start = (const float*)d_in[2];
    const float* stop  = (const float*)d_in[3];
    const float* trans = (const float*)d_in[4];
    float*       out   = (float*)d_out;

    crf_forward_kernel<<<BATCH, 32>>>(em, seq, start, stop, trans, out);
}

// round 3
// speedup vs baseline: 1.0364x; 1.0364x over previous
#include <cuda_runtime.h>

#define BATCH    1024
#define NS       64
#define WPB      4                  // warps (=batches) per block -> SMSP spread
#define F2_T     (BATCH * NS / 2)   // float2 stride per timestep = 32768
#define SHIFT_C  4.5f
#define RESCALE_CHUNKS 4            // rescale every 4 chunks * 4 steps = 16 steps

// ---- packed f32x2 helpers (sm_103a) ----
__device__ __forceinline__ unsigned long long ffma2(unsigned long long a,
                                                    unsigned long long b,
                                                    unsigned long long c) {
    unsigned long long d;
    asm("fma.rn.f32x2 %0, %1, %2, %3;" : "=l"(d) : "l"(a), "l"(b), "l"(c));
    return d;
}
__device__ __forceinline__ unsigned long long fadd2(unsigned long long a,
                                                    unsigned long long b) {
    unsigned long long d;
    asm("add.rn.f32x2 %0, %1, %2;" : "=l"(d) : "l"(a), "l"(b));
    return d;
}
__device__ __forceinline__ unsigned long long pack2(float lo, float hi) {
    unsigned long long d;
    asm("mov.b64 %0, {%1, %2};" : "=l"(d)
        : "r"(__float_as_uint(lo)), "r"(__float_as_uint(hi)));
    return d;
}
__device__ __forceinline__ float lo32(unsigned long long v) {
    return __uint_as_float((unsigned)(v & 0xffffffffull));
}
__device__ __forceinline__ float hi32(unsigned long long v) {
    return __uint_as_float((unsigned)(v >> 32));
}

__global__ void __launch_bounds__(WPB * 32, 2)
crf_forward_kernel(const float* __restrict__ em,
                   const int*   __restrict__ seq,
                   const float* __restrict__ start,
                   const float* __restrict__ stop,
                   const float* __restrict__ trans,
                   float*       __restrict__ out)
{
    // per-warp double-buffered alpha (linear domain, drifting scale)
    __shared__ __align__(16) float2 abuf[2][WPB][NS / 2];

    const int w    = threadIdx.x >> 5;
    const int lane = threadIdx.x & 31;
    const int b    = blockIdx.x * WPB + w;

    // ---- one-time: E = exp(trans - c) for my two output states, in regs ----
    unsigned long long E0[32], E1[32];
    {
        const float4* tr0 = (const float4*)(trans + (2 * lane)     * NS);
        const float4* tr1 = (const float4*)(trans + (2 * lane + 1) * NS);
#pragma unroll
        for (int j = 0; j < 16; j++) {
            float4 r0 = __ldg(tr0 + j);
            float4 r1 = __ldg(tr1 + j);
            E0[2 * j]     = pack2(__expf(r0.x - SHIFT_C), __expf(r0.y - SHIFT_C));
            E0[2 * j + 1] = pack2(__expf(r0.z - SHIFT_C), __expf(r0.w - SHIFT_C));
            E1[2 * j]     = pack2(__expf(r1.x - SHIFT_C), __expf(r1.y - SHIFT_C));
            E1[2 * j + 1] = pack2(__expf(r1.z - SHIFT_C), __expf(r1.w - SHIFT_C));
        }
    }

    const int L = seq[b];
    const float2* embase = (const float2*)em + (unsigned)b * (NS / 2) + lane;

    // ---- init: a = exp(start + em_0) ----
    float2 st2 = ((const float2*)start)[lane];
    float2 em0 = __ldg(embase);
    float2 cur;
    cur.x = __expf(st2.x + em0.x);
    cur.y = __expf(st2.y + em0.y);
    abuf[0][w][lane] = cur;
    float C = 0.0f;
    float2 sp2 = ((const float2*)stop)[lane];
    const float estop0 = __expf(sp2.x);
    const float estop1 = __expf(sp2.y);
    __syncwarp();

    // ---- 4-deep emission prefetch ring (exp applied at load, off-chain) ----
    float2 ring[4];
#pragma unroll
    for (int i = 0; i < 4; i++) {
        int tt = 1 + i;
        if (tt < L) {
            float2 e = __ldg(embase + (unsigned)tt * F2_T);
            ring[i].x = __expf(e.x);
            ring[i].y = __expf(e.y);
        } else {
            ring[i].x = 1.0f; ring[i].y = 1.0f;
        }
    }

    // One step: read abuf[RD], write abuf[WR], single syncwarp.
#define CRF_BODY(eexp_, RD, WR)                                                \
    do {                                                                       \
        unsigned long long acc00 = 0ull, acc01 = 0ull;                         \
        unsigned long long acc10 = 0ull, acc11 = 0ull;                         \
        const ulonglong2* a2 = (const ulonglong2*)abuf[RD][w];                 \
        _Pragma("unroll")                                                      \
        for (int j = 0; j < 16; j++) {                                         \
            ulonglong2 av = a2[j];                                             \
            acc00 = ffma2(av.x, E0[2 * j],     acc00);                         \
            acc01 = ffma2(av.y, E0[2 * j + 1], acc01);                         \
            acc10 = ffma2(av.x, E1[2 * j],     acc10);                         \
            acc11 = ffma2(av.y, E1[2 * j + 1], acc11);                         \
        }                                                                      \
        unsigned long long va = fadd2(acc00, acc01);                           \
        unsigned long long vb = fadd2(acc10, acc11);                           \
        cur.x = (lo32(va) + hi32(va)) * (eexp_).x;                             \
        cur.y = (lo32(vb) + hi32(vb)) * (eexp_).y;                             \
        abuf[WR][w][lane] = cur;                                               \
        __syncwarp();                                                          \
    } while (0)

#define CRF_STEP(tcur_, slot_, RD, WR)                                         \
    do {                                                                       \
        float2 ee = ring[slot_];                                               \
        int tp = (tcur_) + 4;                                                  \
        if (tp < L) {                                                          \
            float2 e = __ldg(embase + (unsigned)tp * F2_T);                    \
            ring[slot_].x = __expf(e.x);                                       \
            ring[slot_].y = __expf(e.y);                                       \
        }                                                                      \
        CRF_BODY(ee, RD, WR);                                                  \
    } while (0)

    int t = 1;
    int resc = RESCALE_CHUNKS;
    for (; t + 3 < L; t += 4) {
        CRF_STEP(t,     0, 0, 1);
        CRF_STEP(t + 1, 1, 1, 0);
        CRF_STEP(t + 2, 2, 0, 1);
        CRF_STEP(t + 3, 3, 1, 0);
        if (--resc == 0) {                 // every 16 steps: exact rescale
            resc = RESCALE_CHUNKS;
            float m = __shfl_sync(0xffffffffu, cur.x, 0);
            m = fmaxf(m, 1e-30f);
            float rv = __fdividef(1.0f, m);
            cur.x *= rv; cur.y *= rv;
            abuf[0][w][lane] = cur;        // parity is back at buf0
            __syncwarp();
            C += __logf(m);
        }
    }
    // tail: up to 3 steps, parities continue 0->1, 1->0, 0->1
    if (t < L) { CRF_BODY(ring[0], 0, 1); t++; }
    if (t < L) { CRF_BODY(ring[1], 1, 0); t++; }
    if (t < L) { CRF_BODY(ring[2], 0, 1); }

    // ---- finalize: logZ = log(sum_s a[s]*exp(stop[s])) + C + c*(L-1) ----
    float z = cur.x * estop0 + cur.y * estop1;
#pragma unroll
    for (int o = 16; o; o >>= 1)
        z += __shfl_xor_sync(0xffffffffu, z, o);
    if (lane == 0)
        out[b] = __logf(z) + C + SHIFT_C * (float)(L - 1);
}

extern "C" void kernel_launch(void* const* d_in, const int* in_sizes, int n_in,
                              void* d_out, int out_size)
{
    const float* em    = (const float*)d_in[0];
    const int*   seq   = (const int*)d_in[1];
    const float* start = (const float*)d_in[2];
    const float* stop  = (const float*)d_in[3];
    const float* trans = (const float*)d_in[4];
    float*       out   = (float*)d_out;

    crf_forward_kernel<<<BATCH / WPB, WPB * 32>>>(em, seq, start, stop, trans, out);
}

// round 4
// speedup vs baseline: 1.6091x; 1.5526x over previous
#include <cuda_runtime.h>

#define BATCH    1024
#define NS       64
#define WPB      4                  // warps (=batches) per block
#define F2_T     (BATCH * NS / 2)   // float2 stride per timestep = 32768
#define SHIFT_C  4.5f

// ---- packed f32x2 helpers (sm_103a) ----
__device__ __forceinline__ unsigned long long ffma2(unsigned long long a,
                                                    unsigned long long b,
                                                    unsigned long long c) {
    unsigned long long d;
    asm("fma.rn.f32x2 %0, %1, %2, %3;" : "=l"(d) : "l"(a), "l"(b), "l"(c));
    return d;
}
__device__ __forceinline__ unsigned long long fadd2(unsigned long long a,
                                                    unsigned long long b) {
    unsigned long long d;
    asm("add.rn.f32x2 %0, %1, %2;" : "=l"(d) : "l"(a), "l"(b));
    return d;
}
__device__ __forceinline__ unsigned long long pack2(float lo, float hi) {
    unsigned long long d;
    asm("mov.b64 %0, {%1, %2};" : "=l"(d)
        : "r"(__float_as_uint(lo)), "r"(__float_as_uint(hi)));
    return d;
}
__device__ __forceinline__ float lo32(unsigned long long v) {
    return __uint_as_float((unsigned)(v & 0xffffffffull));
}
__device__ __forceinline__ float hi32(unsigned long long v) {
    return __uint_as_float((unsigned)(v >> 32));
}

__global__ void __launch_bounds__(WPB * 32, 2)
crf_forward_kernel(const float* __restrict__ em,
                   const int*   __restrict__ seq,
                   const float* __restrict__ start,
                   const float* __restrict__ stop,
                   const float* __restrict__ trans,
                   float*       __restrict__ out)
{
    // per-warp double-buffered alpha (linear domain, drifting scale)
    __shared__ __align__(16) float2 abuf[2][WPB][NS / 2];

    const int w    = threadIdx.x >> 5;
    const int lane = threadIdx.x & 31;
    const int b    = blockIdx.x * WPB + w;

    // ---- one-time: E = exp(trans - c) for my two output states, in regs ----
    unsigned long long E0[32], E1[32];
    {
        const float4* tr0 = (const float4*)(trans + (2 * lane)     * NS);
        const float4* tr1 = (const float4*)(trans + (2 * lane + 1) * NS);
#pragma unroll
        for (int j = 0; j < 16; j++) {
            float4 r0 = __ldg(tr0 + j);
            float4 r1 = __ldg(tr1 + j);
            E0[2 * j]     = pack2(__expf(r0.x - SHIFT_C), __expf(r0.y - SHIFT_C));
            E0[2 * j + 1] = pack2(__expf(r0.z - SHIFT_C), __expf(r0.w - SHIFT_C));
            E1[2 * j]     = pack2(__expf(r1.x - SHIFT_C), __expf(r1.y - SHIFT_C));
            E1[2 * j + 1] = pack2(__expf(r1.z - SHIFT_C), __expf(r1.w - SHIFT_C));
        }
    }

    const int L    = seq[b];
    const int Lm1  = L - 1;
    const float2* embase = (const float2*)em + (unsigned)b * (NS / 2) + lane;

    // ---- init: a = exp(start + em_0) ----
    float2 st2 = ((const float2*)start)[lane];
    float2 em0 = __ldg(embase);
    float2 cur;
    cur.x = __expf(st2.x + em0.x);
    cur.y = __expf(st2.y + em0.y);
    abuf[0][w][lane] = cur;
    float C = 0.0f;
    float2 sp2 = ((const float2*)stop)[lane];
    const float estop0 = __expf(sp2.x);
    const float estop1 = __expf(sp2.y);
    __syncwarp();

    // ---- 8-deep RAW emission prefetch ring (exp applied at consumption) ----
    float2 ring[8];
#pragma unroll
    for (int i = 0; i < 8; i++) {
        int tt = (1 + i < Lm1) ? (1 + i) : Lm1;   // clamp, branch-free, in-bounds
        ring[i] = __ldg(embase + (unsigned)tt * F2_T);
    }

    // One step: read abuf[RD], write abuf[WR], single syncwarp.
    // eraw_ is a RAW emission (loaded >=8 steps ago); exp applied here, off the
    // load's critical path.
#define CRF_BODY(eraw_, RD, WR)                                                \
    do {                                                                       \
        float eA = __expf((eraw_).x);                                          \
        float eB = __expf((eraw_).y);                                          \
        unsigned long long acc00 = 0ull, acc01 = 0ull;                         \
        unsigned long long acc10 = 0ull, acc11 = 0ull;                         \
        const ulonglong2* a2 = (const ulonglong2*)abuf[RD][w];                 \
        _Pragma("unroll")                                                      \
        for (int j = 0; j < 16; j++) {                                         \
            ulonglong2 av = a2[j];                                             \
            acc00 = ffma2(av.x, E0[2 * j],     acc00);                         \
            acc01 = ffma2(av.y, E0[2 * j + 1], acc01);                         \
            acc10 = ffma2(av.x, E1[2 * j],     acc10);                         \
            acc11 = ffma2(av.y, E1[2 * j + 1], acc11);                         \
        }                                                                      \
        unsigned long long va = fadd2(acc00, acc01);                           \
        unsigned long long vb = fadd2(acc10, acc11);                           \
        cur.x = (lo32(va) + hi32(va)) * eA;                                    \
        cur.y = (lo32(vb) + hi32(vb)) * eB;                                    \
        abuf[WR][w][lane] = cur;                                               \
        __syncwarp();                                                          \
    } while (0)

    // Step with branch-free clamped prefetch: refills slot with t+8 (or Lm1).
#define CRF_STEP(tcur_, slot_, RD, WR)                                         \
    do {                                                                       \
        float2 eraw = ring[slot_];                                             \
        int tp = (tcur_) + 8;                                                  \
        tp = (tp < Lm1) ? tp : Lm1;                                            \
        ring[slot_] = __ldg(embase + (unsigned)tp * F2_T);                     \
        CRF_BODY(eraw, RD, WR);                                                \
    } while (0)

    int t = 1;
    int resc = 2;                          // rescale every 2 iters * 8 steps = 16
    for (; t + 7 < L; t += 8) {
        CRF_STEP(t,     0, 0, 1);
        CRF_STEP(t + 1, 1, 1, 0);
        CRF_STEP(t + 2, 2, 0, 1);
        CRF_STEP(t + 3, 3, 1, 0);
        CRF_STEP(t + 4, 4, 0, 1);
        CRF_STEP(t + 5, 5, 1, 0);
        CRF_STEP(t + 6, 6, 0, 1);
        CRF_STEP(t + 7, 7, 1, 0);
        if (--resc == 0) {                 // every 16 steps: exact rescale
            resc = 2;
            float m = __shfl_sync(0xffffffffu, cur.x, 0);
            m = fmaxf(m, 1e-30f);
            float rv = __fdividef(1.0f, m);
            cur.x *= rv; cur.y *= rv;
            abuf[0][w][lane] = cur;        // parity is back at buf0
            __syncwarp();
            C += __logf(m);
        }
    }
    // tail: up to 7 steps; parity starts at 0 (8 steps per iter keeps it even)
    if (t < L) { CRF_BODY(ring[0], 0, 1); t++; }
    if (t < L) { CRF_BODY(ring[1], 1, 0); t++; }
    if (t < L) { CRF_BODY(ring[2], 0, 1); t++; }
    if (t < L) { CRF_BODY(ring[3], 1, 0); t++; }
    if (t < L) { CRF_BODY(ring[4], 0, 1); t++; }
    if (t < L) { CRF_BODY(ring[5], 1, 0); t++; }
    if (t < L) { CRF_BODY(ring[6], 0, 1); }

    // ---- finalize: logZ = log(sum_s a[s]*exp(stop[s])) + C + c*(L-1) ----
    float z = cur.x * estop0 + cur.y * estop1;
#pragma unroll
    for (int o = 16; o; o >>= 1)
        z += __shfl_xor_sync(0xffffffffu, z, o);
    if (lane == 0)
        out[b] = __logf(z) + C + SHIFT_C * (float)(L - 1);
}

extern "C" void kernel_launch(void* const* d_in, const int* in_sizes, int n_in,
                              void* d_out, int out_size)
{
    const float* em    = (const float*)d_in[0];
    const int*   seq   = (const int*)d_in[1];
    const float* start = (const float*)d_in[2];
    const float* stop  = (const float*)d_in[3];
    const float* trans = (const float*)d_in[4];
    float*       out   = (float*)d_out;

    crf_forward_kernel<<<BATCH / WPB, WPB * 32>>>(em, seq, start, stop, trans, out);
}

// round 5
// speedup vs baseline: 2.1029x; 1.3069x over previous
#include <cuda_runtime.h>

#define BATCH    1024
#define NS       64
#define WPB      8                  // 8 warps/block, 1 block/SM; warp j & j+4 share SMSP j
#define F2_T     (BATCH * NS / 2)   // float2 stride per timestep = 32768
#define SHIFT_C  4.5f

__device__ int g_perm[BATCH];       // rank (desc by length) -> batch index

// ---- packed f32x2 helpers (sm_103a) ----
__device__ __forceinline__ unsigned long long ffma2(unsigned long long a,
                                                    unsigned long long b,
                                                    unsigned long long c) {
    unsigned long long d;
    asm("fma.rn.f32x2 %0, %1, %2, %3;" : "=l"(d) : "l"(a), "l"(b), "l"(c));
    return d;
}
__device__ __forceinline__ unsigned long long fadd2(unsigned long long a,
                                                    unsigned long long b) {
    unsigned long long d;
    asm("add.rn.f32x2 %0, %1, %2;" : "=l"(d) : "l"(a), "l"(b));
    return d;
}
__device__ __forceinline__ unsigned long long pack2(float lo, float hi) {
    unsigned long long d;
    asm("mov.b64 %0, {%1, %2};" : "=l"(d)
        : "r"(__float_as_uint(lo)), "r"(__float_as_uint(hi)));
    return d;
}
__device__ __forceinline__ float lo32(unsigned long long v) {
    return __uint_as_float((unsigned)(v & 0xffffffffull));
}
__device__ __forceinline__ float hi32(unsigned long long v) {
    return __uint_as_float((unsigned)(v >> 32));
}

// ---- rank by length (descending), ties by index: perm is a bijection ----
__global__ void rank_kernel(const int* __restrict__ seq) {
    __shared__ int len[BATCH];
    const int tid = threadIdx.x;             // 128 threads
    for (int j = tid; j < BATCH; j += 128) len[j] = seq[j];
    __syncthreads();
    const int i  = blockIdx.x * 128 + tid;
    const int li = len[i];
    int r = 0;
#pragma unroll 8
    for (int j = 0; j < BATCH; j++) {
        int lj = len[j];
        r += (int)((lj > li) | ((lj == li) & (j < i)));
    }
    g_perm[r] = i;
}

__global__ void __launch_bounds__(WPB * 32, 1)
crf_forward_kernel(const float* __restrict__ em,
                   const int*   __restrict__ seq,
                   const float* __restrict__ start,
                   const float* __restrict__ stop,
                   const float* __restrict__ trans,
                   float*       __restrict__ out)
{
    // per-warp double-buffered alpha (linear domain, drifting scale)
    __shared__ __align__(16) float2 abuf[2][WPB][NS / 2];

    const int w    = threadIdx.x >> 5;       // 0..7 ; SMSP = w & 3
    const int lane = threadIdx.x & 31;
    // long ranks on warps 0-3, complementary short ranks on warps 4-7
    const int rank = (w < 4) ? (4 * blockIdx.x + w)
                             : (BATCH - 1 - 4 * blockIdx.x - (w - 4));
    const int b    = g_perm[rank];

    // ---- one-time: E = exp(trans - c) for my two output states, in regs ----
    unsigned long long E0[32], E1[32];
    {
        const float4* tr0 = (const float4*)(trans + (2 * lane)     * NS);
        const float4* tr1 = (const float4*)(trans + (2 * lane + 1) * NS);
#pragma unroll
        for (int j = 0; j < 16; j++) {
            float4 r0 = __ldg(tr0 + j);
            float4 r1 = __ldg(tr1 + j);
            E0[2 * j]     = pack2(__expf(r0.x - SHIFT_C), __expf(r0.y - SHIFT_C));
            E0[2 * j + 1] = pack2(__expf(r0.z - SHIFT_C), __expf(r0.w - SHIFT_C));
            E1[2 * j]     = pack2(__expf(r1.x - SHIFT_C), __expf(r1.y - SHIFT_C));
            E1[2 * j + 1] = pack2(__expf(r1.z - SHIFT_C), __expf(r1.w - SHIFT_C));
        }
    }

    const int L    = seq[b];
    const int Lm1  = L - 1;
    const float2* embase = (const float2*)em + (unsigned)b * (NS / 2) + lane;

    // ---- init: a = exp(start + em_0) ----
    float2 st2 = ((const float2*)start)[lane];
    float2 em0 = __ldg(embase);
    float2 cur;
    cur.x = __expf(st2.x + em0.x);
    cur.y = __expf(st2.y + em0.y);
    abuf[0][w][lane] = cur;
    float C = 0.0f;
    float2 sp2 = ((const float2*)stop)[lane];
    const float estop0 = __expf(sp2.x);
    const float estop1 = __expf(sp2.y);
    __syncwarp();

    // ---- 8-deep RAW emission prefetch ring (exp applied at consumption) ----
    float2 ring[8];
#pragma unroll
    for (int i = 0; i < 8; i++) {
        int tt = (1 + i < Lm1) ? (1 + i) : Lm1;   // clamp, branch-free, in-bounds
        ring[i] = __ldg(embase + (unsigned)tt * F2_T);
    }

    // One step: read abuf[RD], write abuf[WR], single syncwarp.
#define CRF_BODY(eraw_, RD, WR)                                                \
    do {                                                                       \
        float eA = __expf((eraw_).x);                                          \
        float eB = __expf((eraw_).y);                                          \
        unsigned long long acc00 = 0ull, acc01 = 0ull;                         \
        unsigned long long acc10 = 0ull, acc11 = 0ull;                         \
        const ulonglong2* a2 = (const ulonglong2*)abuf[RD][w];                 \
        _Pragma("unroll")                                                      \
        for (int j = 0; j < 16; j++) {                                         \
            ulonglong2 av = a2[j];                                             \
            acc00 = ffma2(av.x, E0[2 * j],     acc00);                         \
            acc01 = ffma2(av.y, E0[2 * j + 1], acc01);                         \
            acc10 = ffma2(av.x, E1[2 * j],     acc10);                         \
            acc11 = ffma2(av.y, E1[2 * j + 1], acc11);                         \
        }                                                                      \
        unsigned long long va = fadd2(acc00, acc01);                           \
        unsigned long long vb = fadd2(acc10, acc11);                           \
        cur.x = (lo32(va) + hi32(va)) * eA;                                    \
        cur.y = (lo32(vb) + hi32(vb)) * eB;                                    \
        abuf[WR][w][lane] = cur;                                               \
        __syncwarp();                                                          \
    } while (0)

    // Step with branch-free clamped prefetch: refills slot with t+8 (or Lm1).
#define CRF_STEP(tcur_, slot_, RD, WR)                                         \
    do {                                                                       \
        float2 eraw = ring[slot_];                                             \
        int tp = (tcur_) + 8;                                                  \
        tp = (tp < Lm1) ? tp : Lm1;                                            \
        ring[slot_] = __ldg(embase + (unsigned)tp * F2_T);                     \
        CRF_BODY(eraw, RD, WR);                                                \
    } while (0)

    int t = 1;
    int resc = 2;                          // rescale every 2 iters * 8 steps = 16
    for (; t + 7 < L; t += 8) {
        CRF_STEP(t,     0, 0, 1);
        CRF_STEP(t + 1, 1, 1, 0);
        CRF_STEP(t + 2, 2, 0, 1);
        CRF_STEP(t + 3, 3, 1, 0);
        CRF_STEP(t + 4, 4, 0, 1);
        CRF_STEP(t + 5, 5, 1, 0);
        CRF_STEP(t + 6, 6, 0, 1);
        CRF_STEP(t + 7, 7, 1, 0);
        if (--resc == 0) {                 // every 16 steps: exact rescale
            resc = 2;
            float m = __shfl_sync(0xffffffffu, cur.x, 0);
            m = fmaxf(m, 1e-30f);
            float rv = __fdividef(1.0f, m);
            cur.x *= rv; cur.y *= rv;
            abuf[0][w][lane] = cur;        // parity is back at buf0
            __syncwarp();
            C += __logf(m);
        }
    }
    // tail: up to 7 steps; parity starts at 0 (8 steps per iter keeps it even)
    if (t < L) { CRF_BODY(ring[0], 0, 1); t++; }
    if (t < L) { CRF_BODY(ring[1], 1, 0); t++; }
    if (t < L) { CRF_BODY(ring[2], 0, 1); t++; }
    if (t < L) { CRF_BODY(ring[3], 1, 0); t++; }
    if (t < L) { CRF_BODY(ring[4], 0, 1); t++; }
    if (t < L) { CRF_BODY(ring[5], 1, 0); t++; }
    if (t < L) { CRF_BODY(ring[6], 0, 1); }

    // ---- finalize: logZ = log(sum_s a[s]*exp(stop[s])) + C + c*(L-1) ----
    float z = cur.x * estop0 + cur.y * estop1;
#pragma unroll
    for (int o = 16; o; o >>= 1)
        z += __shfl_xor_sync(0xffffffffu, z, o);
    if (lane == 0)
        out[b] = __logf(z) + C + SHIFT_C * (float)(L - 1);
}

extern "C" void kernel_launch(void* const* d_in, const int* in_sizes, int n_in,
                              void* d_out, int out_size)
{
    const float* em    = (const float*)d_in[0];
    const int*   seq   = (const int*)d_in[1];
    const float* start = (const float*)d_in[2];
    const float* stop  = (const float*)d_in[3];
    const float* trans = (const float*)d_in[4];
    float*       out   = (float*)d_out;

    rank_kernel<<<BATCH / 128, 128>>>(seq);
    crf_forward_kernel<<<BATCH / WPB, WPB * 32>>>(em, seq, start, stop, trans, out);
}